// round 1
// baseline (speedup 1.0000x reference)
#include <cuda_runtime.h>
#include <cstdint>

#define B_ 8
#define N_ 256
#define L_ 48
#define F_ 96
#define LF (L_*F_)
#define XS 260   // padded position stride for [l][pos] smem tiles

typedef unsigned long long ull;

// ---------------- scratch (no allocation allowed) ----------------
__device__ float g_rowsum[B_*N_*L_];
__device__ float g_colsum[B_*N_*L_];
__device__ float g_diag  [B_*N_*L_];
__device__ float g_dscal [B_*F_];
__device__ float g_scal  [B_*F_];
__device__ float g_diagA [B_*N_*F_];
__device__ float g_bi    [B_*N_*F_];
__device__ float g_bjs   [B_*N_*F_];

// ---------------- f32x2 helpers (Blackwell packed FFMA) ----------------
__device__ __forceinline__ ull pk2(float a){
    ull r; asm("mov.b64 %0, {%1,%1};" : "=l"(r) : "f"(a)); return r;
}
__device__ __forceinline__ ull ffma2(ull a, ull b, ull c){
    ull d; asm("fma.rn.f32x2 %0, %1, %2, %3;" : "=l"(d) : "l"(a), "l"(b), "l"(c)); return d;
}
__device__ __forceinline__ void upk(ull v, float &a, float &b){
    asm("mov.b64 {%0,%1}, %2;" : "=f"(a), "=f"(b) : "l"(v));
}

// ---------------- K1: rowsum[b,i,l] = sum_j x[b,i,j,l]; diag[b,i,l] ----------------
__global__ void k_rowsum(const float* __restrict__ x){
    const int i = blockIdx.x, b = blockIdx.y;
    const int t = threadIdx.x;
    const int l = t % 48, q = t / 48;
    __shared__ float sp[192];
    const float* xr = x + ((size_t)(b*N_ + i))*N_*L_;
    float acc = 0.f;
    for (int j = q; j < N_; j += 4) acc += __ldg(xr + j*L_ + l);
    sp[t] = acc;
    __syncthreads();
    if (q == 0){
        g_rowsum[(b*N_+i)*L_ + l] = sp[l] + sp[48+l] + sp[96+l] + sp[144+l];
        g_diag  [(b*N_+i)*L_ + l] = __ldg(xr + i*L_ + l);
    }
}

// ---------------- K2: colsum[b,j,l] = sum_i x[b,i,j,l] ----------------
__global__ void k_colsum(const float* __restrict__ x){
    const int j = blockIdx.x, b = blockIdx.y;
    const int t = threadIdx.x;
    const int l = t % 48, q = t / 48;
    __shared__ float sp[192];
    const float* xb = x + ((size_t)b)*N_*N_*L_;
    float acc = 0.f;
    for (int i = q; i < N_; i += 4) acc += __ldg(xb + ((size_t)i*N_ + j)*L_ + l);
    sp[t] = acc;
    __syncthreads();
    if (q == 0){
        g_colsum[(b*N_+j)*L_ + l] = sp[l] + sp[48+l] + sp[96+l] + sp[144+l];
    }
}

// ---------------- K3: trace/totsum -> per-batch scalar projections ----------------
__global__ void k_scal(const float* __restrict__ w){
    const int b = blockIdx.x;
    const int t = threadIdx.x;   // 96 threads = f
    __shared__ float tr[48], ts[48];
    if (t < 48){
        float a = 0.f, s = 0.f;
        for (int i = 0; i < N_; i++){
            a += g_diag  [(b*N_+i)*L_ + t];
            s += g_rowsum[(b*N_+i)*L_ + t];
        }
        tr[t] = a; ts[t] = s;
    }
    __syncthreads();
    float ds = 0.f, sc = 0.f;
    for (int l = 0; l < 48; l++){
        float a = tr[l], s = ts[l];
        ds += a*__ldg(w +  3*LF + l*F_ + t) + s*__ldg(w +  4*LF + l*F_ + t);
        sc += a*__ldg(w + 13*LF + l*F_ + t) + s*__ldg(w + 14*LF + l*F_ + t);
    }
    g_dscal[b*F_ + t] = ds;
    g_scal [b*F_ + t] = sc;
}

// ---------------- K4: per-node projections diagA / bjs / bi ----------------
__global__ void k_node(const float* __restrict__ w){
    const int n = blockIdx.x, b = blockIdx.y;
    const int t = threadIdx.x;   // 96 threads = f
    __shared__ float d_[48], r_[48], c_[48];
    const int base = (b*N_ + n)*L_;
    if (t < 48){
        d_[t] = g_diag  [base + t];
        r_[t] = g_rowsum[base + t];
        c_[t] = g_colsum[base + t];
    }
    __syncthreads();
    float aA = g_dscal[b*F_ + t];
    float aJ = g_scal [b*F_ + t];
    float aI = 0.f;
    for (int l = 0; l < 48; l++){
        const float dd = d_[l], rr = r_[l], cc = c_[l];
        const float* wl = w + l*F_ + t;
        aA += dd*__ldg(wl        ) + rr*__ldg(wl +    LF) + cc*__ldg(wl +  2*LF);
        aJ += dd*__ldg(wl +  5*LF) + rr*__ldg(wl +  6*LF) + cc*__ldg(wl +  7*LF);
        aI += dd*__ldg(wl +  8*LF) + rr*__ldg(wl +  9*LF) + cc*__ldg(wl + 10*LF);
    }
    const int o = (b*N_ + n)*F_ + t;
    g_diagA[o] = aA;
    g_bjs  [o] = aJ;
    g_bi   [o] = aI;
}

// ---------------- Main fused kernel ----------------
// 16x16 (i,j) tile per block. out[b,i,j,f] = x[b,i,j,:]@w12 + x[b,j,i,:]@w11
//                                          + bi[b,i,f] + bjs[b,j,f] (+ diagA if i==j)
__global__ __launch_bounds__(256, 1)
void k_main(const float* __restrict__ x, const float* __restrict__ w,
            float* __restrict__ out){
    const int jt = blockIdx.x, it = blockIdx.y, b = blockIdx.z;
    const int i0 = it*16, j0 = jt*16;
    const int tid = threadIdx.x;

    extern __shared__ float sm[];
    float* xd    = sm;                 // [48][XS]
    float* xt    = xd  + 48*XS;        // [48][XS]
    float* w12s  = xt  + 48*XS;        // [48][96]
    float* w11s  = w12s + 48*96;       // [48][96]
    float* bis   = w11s + 48*96;       // [16][96]
    float* bjs_s = bis  + 16*96;       // [16][96]

    // ---- stage w11 / w12 ----
    const float* w11g = w + 11*LF;
    const float* w12g = w + 12*LF;
    for (int idx = tid; idx < LF; idx += 256){
        w12s[idx] = __ldg(w12g + idx);
        w11s[idx] = __ldg(w11g + idx);
    }
    // ---- stage bi / bjs tiles ----
    for (int idx = tid; idx < 16*F_; idx += 256){
        const int r = idx / F_, f = idx % F_;
        bis  [idx] = g_bi [(b*N_ + i0 + r)*F_ + f];
        bjs_s[idx] = g_bjs[(b*N_ + j0 + r)*F_ + f];
    }
    // ---- stage x tiles (direct + transposed), [l][pos] layout ----
    const float* xb = x + ((size_t)b)*N_*N_*L_;
    for (int idx4 = tid; idx4 < 3072; idx4 += 256){
        const int ti  = idx4 / 192;
        const int rem = idx4 % 192;
        const int tj  = rem / 12;
        const int l4  = (rem % 12)*4;
        float4 v = *(const float4*)(xb + (size_t)(i0+ti)*N_*L_ + (size_t)(j0+tj)*L_ + l4);
        const int p = ti*16 + tj;
        xd[(l4+0)*XS + p] = v.x; xd[(l4+1)*XS + p] = v.y;
        xd[(l4+2)*XS + p] = v.z; xd[(l4+3)*XS + p] = v.w;
    }
    for (int idx4 = tid; idx4 < 3072; idx4 += 256){
        const int tj  = idx4 / 192;
        const int rem = idx4 % 192;
        const int ti  = rem / 12;
        const int l4  = (rem % 12)*4;
        float4 v = *(const float4*)(xb + (size_t)(j0+tj)*N_*L_ + (size_t)(i0+ti)*L_ + l4);
        const int p = ti*16 + tj;
        xt[(l4+0)*XS + p] = v.x; xt[(l4+1)*XS + p] = v.y;
        xt[(l4+2)*XS + p] = v.z; xt[(l4+3)*XS + p] = v.w;
    }
    __syncthreads();

    // ---- register-tiled compute: 8 positions x 12 features per thread ----
    const int fg = tid & 7;        // 8 feature groups
    const int pg = tid >> 3;       // 32 position groups
    const int f0 = fg * 12;
    const int p0 = pg * 8;

    ull acc[48];
    #pragma unroll
    for (int q = 0; q < 48; q++) acc[q] = 0ULL;

    const float* xdp = xd   + p0;
    const float* xtp = xt   + p0;
    const float* w2p = w12s + f0;
    const float* w1p = w11s + f0;

    #pragma unroll 4
    for (int l = 0; l < 48; l++){
        float4 a0 = *(const float4*)(xdp + l*XS);
        float4 a1 = *(const float4*)(xdp + l*XS + 4);
        float4 b0 = *(const float4*)(xtp + l*XS);
        float4 b1 = *(const float4*)(xtp + l*XS + 4);
        ull w2[6], w1[6];
        #pragma unroll
        for (int q = 0; q < 6; q++){
            w2[q] = *(const ull*)(w2p + l*F_ + 2*q);
            w1[q] = *(const ull*)(w1p + l*F_ + 2*q);
        }
        const float xa[8] = {a0.x,a0.y,a0.z,a0.w,a1.x,a1.y,a1.z,a1.w};
        const float xc[8] = {b0.x,b0.y,b0.z,b0.w,b1.x,b1.y,b1.z,b1.w};
        #pragma unroll
        for (int p = 0; p < 8; p++){
            const ull da = pk2(xa[p]);
            const ull db = pk2(xc[p]);
            #pragma unroll
            for (int q = 0; q < 6; q++){
                acc[p*6+q] = ffma2(da, w2[q], acc[p*6+q]);
                acc[p*6+q] = ffma2(db, w1[q], acc[p*6+q]);
            }
        }
    }

    // ---- epilogue ----
    const int ti  = pg >> 1;             // thread's positions live in one i-row
    const int tjb = (pg & 1) * 8;
    const int gi  = i0 + ti;

    float bic[12];
    {
        const float* bp = bis + ti*F_ + f0;
        #pragma unroll
        for (int q = 0; q < 12; q++) bic[q] = bp[q];
    }
    float* orow = out + (((size_t)(b*N_ + gi))*N_ + j0)*F_ + f0;

    #pragma unroll
    for (int p = 0; p < 8; p++){
        const int tj = tjb + p;
        float v[12];
        #pragma unroll
        for (int q = 0; q < 6; q++) upk(acc[p*6+q], v[2*q], v[2*q+1]);
        const float* jp = bjs_s + tj*F_ + f0;
        #pragma unroll
        for (int q = 0; q < 12; q++) v[q] += bic[q] + jp[q];
        if (gi == j0 + tj){
            const float* dp = g_diagA + (size_t)(b*N_ + gi)*F_ + f0;
            #pragma unroll
            for (int q = 0; q < 12; q++) v[q] += __ldg(dp + q);
        }
        float* op = orow + (size_t)tj*F_;
        *(float4*)(op    ) = make_float4(v[0], v[1], v[2],  v[3]);
        *(float4*)(op + 4) = make_float4(v[4], v[5], v[6],  v[7]);
        *(float4*)(op + 8) = make_float4(v[8], v[9], v[10], v[11]);
    }
}

// ---------------- launch ----------------
extern "C" void kernel_launch(void* const* d_in, const int* in_sizes, int n_in,
                              void* d_out, int out_size){
    const float* x = (const float*)d_in[0];
    const float* w = (const float*)d_in[1];
    float* out = (float*)d_out;
    (void)in_sizes; (void)n_in; (void)out_size;

    k_rowsum<<<dim3(N_, B_), 192>>>(x);
    k_colsum<<<dim3(N_, B_), 192>>>(x);
    k_scal  <<<B_, 96>>>(w);
    k_node  <<<dim3(N_, B_), 96>>>(w);

    const size_t smem = (size_t)(2*48*XS + 2*48*96 + 2*16*96) * sizeof(float); // 148992 B
    cudaFuncSetAttribute(k_main, cudaFuncAttributeMaxDynamicSharedMemorySize, (int)smem);
    k_main<<<dim3(16, 16, B_), 256, smem>>>(x, w, out);
}